// round 3
// baseline (speedup 1.0000x reference)
#include <cuda_runtime.h>
#include <math.h>

#define N_NODES 50000
#define N_EDGES 400000
#define SLOPE   0.2f

#define ETILE    64
#define ETHREADS 512
#define NTILES   (N_EDGES / ETILE)   // 6250, exact

// ---------------- scratch (__device__ globals; no allocation allowed) ----------------
__device__ __align__(16) float g_P[(size_t)N_NODES * 128];          // node_emb @ W_upd[0:128]
__device__ __align__(16) float g_star[N_NODES * 8];                 // node_emb @ W_attn[0:128]
__device__ __align__(16) float g_ssrc[N_NODES * 8];                 // node_emb @ W_attn[384:512]
__device__ __align__(16) float g_attrpart[(size_t)N_EDGES * 128];   // attr_emb @ W_upd[128:256]
__device__ __align__(16) float g_ex[N_EDGES * 8];
__device__ __align__(16) float g_denom[N_NODES * 8];
__device__ int g_src[N_EDGES], g_tar[N_EDGES];
__device__ int g_deg[N_NODES], g_off[N_NODES + 1], g_cursor[N_NODES], g_perm[N_EDGES];

__device__ __forceinline__ float lrelu(float x) { return x >= 0.f ? x : SLOPE * x; }

// ---------------- init (indices are INT32) ----------------
__global__ void k_init(const int* __restrict__ eidx) {
    int i = blockIdx.x * blockDim.x + threadIdx.x;
    if (i < N_EDGES) {
        g_src[i] = eidx[i];
        g_tar[i] = eidx[N_EDGES + i];
    }
    if (i < N_NODES * 8) g_denom[i] = 0.f;
    if (i < N_NODES) g_deg[i] = 0;
}

__global__ void k_hist() {
    int i = blockIdx.x * blockDim.x + threadIdx.x;
    if (i < N_EDGES) atomicAdd(&g_deg[g_src[i]], 1);
}

__global__ void k_scan() {
    __shared__ int s[1024];
    const int CH = (N_NODES + 1023) / 1024;
    int t = threadIdx.x;
    int base = t * CH;
    int sum = 0;
    for (int i = 0; i < CH; i++) {
        int idx = base + i;
        if (idx < N_NODES) sum += g_deg[idx];
    }
    s[t] = sum;
    __syncthreads();
    for (int d = 1; d < 1024; d <<= 1) {
        int v = (t >= d) ? s[t - d] : 0;
        __syncthreads();
        s[t] += v;
        __syncthreads();
    }
    int run = (t == 0) ? 0 : s[t - 1];
    for (int i = 0; i < CH; i++) {
        int idx = base + i;
        if (idx < N_NODES) {
            g_off[idx] = run;
            g_cursor[idx] = run;
            run += g_deg[idx];
        }
    }
    if (t == 1023) g_off[N_NODES] = N_EDGES;
}

__global__ void k_scatter() {
    int i = blockIdx.x * blockDim.x + threadIdx.x;
    if (i < N_EDGES) {
        int p = atomicAdd(&g_cursor[g_src[i]], 1);
        g_perm[p] = i;
    }
}

// ---------------- merged node kernel: emb (smem only) -> P, s_tar, s_src ----------------
// dynamic smem: sx[32*256]=8192 floats, se[32*132]=4224 floats
#define NODE_SMEM_BYTES ((8192 + 4224) * 4)

__global__ void k_node(const float* __restrict__ x, const int* __restrict__ ntl,
                       const float* __restrict__ Wn, const float* __restrict__ Wupd,
                       const float* __restrict__ Wattn) {
    extern __shared__ float smn[];
    float* sx = smn;          // 32 x 256
    float* se = smn + 8192;   // 32 x 132 (padded)
    int n0 = blockIdx.x * 32;
    int t = threadIdx.x;

    for (int i = t; i < 2048; i += 256) {       // 32 rows x 64 float4
        int row = i >> 6, c4 = i & 63;
        int node = n0 + row;
        float4 v = make_float4(0.f, 0.f, 0.f, 0.f);
        if (node < N_NODES) v = ((const float4*)(x + (size_t)node * 256))[c4];
        ((float4*)sx)[row * 64 + c4] = v;
    }
    __syncthreads();

    int tx = t & 31, ty = t >> 5;
    int r0 = ty * 4;

    // emb = x @ W_node[type]
    {
        const float* wp[4];
        int nodes[4];
#pragma unroll
        for (int j = 0; j < 4; j++) {
            int node = n0 + r0 + j;
            nodes[j] = node;
            int tp = (node < N_NODES) ? ntl[node] : 0;
            wp[j] = Wn + (size_t)tp * (256 * 128) + tx * 4;
        }
        float acc[4][4];
#pragma unroll
        for (int j = 0; j < 4; j++)
#pragma unroll
            for (int c = 0; c < 4; c++) acc[j][c] = 0.f;
#pragma unroll 4
        for (int k = 0; k < 256; k++) {
#pragma unroll
            for (int j = 0; j < 4; j++) {
                float4 w = *(const float4*)(wp[j] + (size_t)k * 128);
                float xv = sx[(r0 + j) * 256 + k];
                acc[j][0] += xv * w.x; acc[j][1] += xv * w.y;
                acc[j][2] += xv * w.z; acc[j][3] += xv * w.w;
            }
        }
#pragma unroll
        for (int j = 0; j < 4; j++)
            *(float4*)(se + (r0 + j) * 132 + tx * 4) =
                make_float4(acc[j][0], acc[j][1], acc[j][2], acc[j][3]);
    }
    __syncthreads();

    // P = emb @ W_upd[0:128]
    {
        float acc[4][4];
#pragma unroll
        for (int j = 0; j < 4; j++)
#pragma unroll
            for (int c = 0; c < 4; c++) acc[j][c] = 0.f;
#pragma unroll 4
        for (int k = 0; k < 128; k++) {
            float4 w = *(const float4*)(Wupd + (size_t)k * 128 + tx * 4);
#pragma unroll
            for (int j = 0; j < 4; j++) {
                float xv = se[(r0 + j) * 132 + k];
                acc[j][0] += xv * w.x; acc[j][1] += xv * w.y;
                acc[j][2] += xv * w.z; acc[j][3] += xv * w.w;
            }
        }
#pragma unroll
        for (int j = 0; j < 4; j++) {
            int node = n0 + r0 + j;
            if (node < N_NODES)
                *(float4*)(g_P + (size_t)node * 128 + tx * 4) =
                    make_float4(acc[j][0], acc[j][1], acc[j][2], acc[j][3]);
        }
    }

    // s_tar / s_src
    {
        int e = t >> 3, h = t & 7;
        int node = n0 + e;
        float at = 0.f, as = 0.f;
        for (int k = 0; k < 128; k++) {
            float v = se[e * 132 + k];
            at += v * Wattn[k * 8 + h];
            as += v * Wattn[(384 + k) * 8 + h];
        }
        if (node < N_NODES) {
            g_star[node * 8 + h] = at;
            g_ssrc[node * 8 + h] = as;
        }
    }
}

// ---------------- persistent fused edge kernel ----------------
// smem floats: sWea 8192 | sWet 8192 | sWup 16384 | sWaT 2112 | sX 4096 | sA 8448 | sT 8448
#define OF_WEA 0
#define OF_WET 8192
#define OF_WUP 16384
#define OF_WAT 32768
#define OF_X   34880
#define OF_A   38976
#define OF_T   47424
#define EDGE_SMEM_FLOATS 55872
#define EDGE_SMEM_BYTES  (EDGE_SMEM_FLOATS * 4)

__global__ void __launch_bounds__(ETHREADS, 1)
k_edge(const float* __restrict__ eattr, const float* __restrict__ etype,
       const float* __restrict__ Weattr, const float* __restrict__ Wetype,
       const float* __restrict__ Wupd, const float* __restrict__ Wattn) {
    extern __shared__ float sm[];
    float* sWea = sm + OF_WEA;
    float* sWet = sm + OF_WET;
    float* sWup = sm + OF_WUP;
    float* sWaT = sm + OF_WAT;   // [8][264]: k 0..127 attr part, 128..255 type part
    float* sX   = sm + OF_X;     // 64 x 64
    float* sA   = sm + OF_A;     // 64 x 132
    float* sT   = sm + OF_T;     // 64 x 132
    __shared__ int sSrc[ETILE], sTar[ETILE];

    int t = threadIdx.x;

    // stage all weights once
    for (int i = t; i < 2048; i += ETHREADS) ((float4*)sWea)[i] = ((const float4*)Weattr)[i];
    for (int i = t; i < 2048; i += ETHREADS) ((float4*)sWet)[i] = ((const float4*)Wetype)[i];
    for (int i = t; i < 4096; i += ETHREADS) ((float4*)sWup)[i] = ((const float4*)(Wupd + 128 * 128))[i];
    for (int i = t; i < 2048; i += ETHREADS) {
        int k = i >> 3, h = i & 7;
        sWaT[h * 264 + k] = Wattn[(128 + k) * 8 + h];
    }

    int tx = t & 31, ty = t >> 5;   // ty 0..15
    int r0 = ty * 4;
    int se_ = t >> 3, hh = t & 7;   // score-phase mapping (e 0..63, h 0..7)

    for (int tile = blockIdx.x; tile < NTILES; tile += gridDim.x) {
        int e0 = tile * ETILE;
        __syncthreads();   // protect sSrc/sTar/sX from previous tile's readers
        if (t < ETILE) { sSrc[t] = g_src[e0 + t]; sTar[t] = g_tar[e0 + t]; }
        for (int i = t; i < ETILE * 16; i += ETHREADS)
            ((float4*)sX)[i] = ((const float4*)(eattr + (size_t)e0 * 64))[i];
        __syncthreads();

        // phase A: sA = lrelu(sX @ sWea)   [64x64]x[64x128]
        {
            float acc[4][4];
#pragma unroll
            for (int j = 0; j < 4; j++)
#pragma unroll
                for (int c = 0; c < 4; c++) acc[j][c] = 0.f;
#pragma unroll 2
            for (int k0 = 0; k0 < 64; k0 += 4) {
                float4 xv[4];
#pragma unroll
                for (int j = 0; j < 4; j++) xv[j] = *(const float4*)(sX + (r0 + j) * 64 + k0);
#pragma unroll
                for (int kk = 0; kk < 4; kk++) {
                    float4 w = *(const float4*)(sWea + (k0 + kk) * 128 + tx * 4);
#pragma unroll
                    for (int j = 0; j < 4; j++) {
                        float xs = ((const float*)&xv[j])[kk];
                        acc[j][0] += xs * w.x; acc[j][1] += xs * w.y;
                        acc[j][2] += xs * w.z; acc[j][3] += xs * w.w;
                    }
                }
            }
#pragma unroll
            for (int j = 0; j < 4; j++)
                *(float4*)(sA + (r0 + j) * 132 + tx * 4) =
                    make_float4(lrelu(acc[j][0]), lrelu(acc[j][1]), lrelu(acc[j][2]), lrelu(acc[j][3]));
        }
        __syncthreads();   // A done; sX reusable

        for (int i = t; i < ETILE * 16; i += ETHREADS)
            ((float4*)sX)[i] = ((const float4*)(etype + (size_t)e0 * 64))[i];
        __syncthreads();

        // phase T: sT = lrelu(sX @ sWet)
        {
            float acc[4][4];
#pragma unroll
            for (int j = 0; j < 4; j++)
#pragma unroll
                for (int c = 0; c < 4; c++) acc[j][c] = 0.f;
#pragma unroll 2
            for (int k0 = 0; k0 < 64; k0 += 4) {
                float4 xv[4];
#pragma unroll
                for (int j = 0; j < 4; j++) xv[j] = *(const float4*)(sX + (r0 + j) * 64 + k0);
#pragma unroll
                for (int kk = 0; kk < 4; kk++) {
                    float4 w = *(const float4*)(sWet + (k0 + kk) * 128 + tx * 4);
#pragma unroll
                    for (int j = 0; j < 4; j++) {
                        float xs = ((const float*)&xv[j])[kk];
                        acc[j][0] += xs * w.x; acc[j][1] += xs * w.y;
                        acc[j][2] += xs * w.z; acc[j][3] += xs * w.w;
                    }
                }
            }
#pragma unroll
            for (int j = 0; j < 4; j++)
                *(float4*)(sT + (r0 + j) * 132 + tx * 4) =
                    make_float4(lrelu(acc[j][0]), lrelu(acc[j][1]), lrelu(acc[j][2]), lrelu(acc[j][3]));
        }
        __syncthreads();   // A and T visible

        // phase P: g_attrpart = sA @ sWup   [64x128]x[128x128]
        {
            float acc[4][4];
#pragma unroll
            for (int j = 0; j < 4; j++)
#pragma unroll
                for (int c = 0; c < 4; c++) acc[j][c] = 0.f;
#pragma unroll 2
            for (int k0 = 0; k0 < 128; k0 += 4) {
                float4 av[4];
#pragma unroll
                for (int j = 0; j < 4; j++) av[j] = *(const float4*)(sA + (r0 + j) * 132 + k0);
#pragma unroll
                for (int kk = 0; kk < 4; kk++) {
                    float4 w = *(const float4*)(sWup + (k0 + kk) * 128 + tx * 4);
#pragma unroll
                    for (int j = 0; j < 4; j++) {
                        float xs = ((const float*)&av[j])[kk];
                        acc[j][0] += xs * w.x; acc[j][1] += xs * w.y;
                        acc[j][2] += xs * w.z; acc[j][3] += xs * w.w;
                    }
                }
            }
#pragma unroll
            for (int j = 0; j < 4; j++)
                *(float4*)(g_attrpart + (size_t)(e0 + r0 + j) * 128 + tx * 4) =
                    make_float4(acc[j][0], acc[j][1], acc[j][2], acc[j][3]);
        }

        // scores: one thread per (edge, head)
        {
            int src = sSrc[se_], tar = sTar[se_];
            float sc = g_star[tar * 8 + hh] + g_ssrc[src * 8 + hh];
            float s0 = 0.f, s1 = 0.f, s2 = 0.f, s3 = 0.f;
#pragma unroll 4
            for (int k = 0; k < 128; k += 4) {
                float4 a = *(const float4*)(sA + se_ * 132 + k);
                float4 w = *(const float4*)(sWaT + hh * 264 + k);
                s0 += a.x * w.x; s1 += a.y * w.y; s2 += a.z * w.z; s3 += a.w * w.w;
                float4 tv = *(const float4*)(sT + se_ * 132 + k);
                float4 w2 = *(const float4*)(sWaT + hh * 264 + 128 + k);
                s0 += tv.x * w2.x; s1 += tv.y * w2.y; s2 += tv.z * w2.z; s3 += tv.w * w2.w;
            }
            sc += (s0 + s1) + (s2 + s3);
            sc = lrelu(sc);
            float ex = expf(sc);
            g_ex[(e0 + se_) * 8 + hh] = ex;
            atomicAdd(&g_denom[src * 8 + hh], ex);
        }
    }
}

// ---------------- aggregation ----------------
__global__ void k_aggr(float* __restrict__ out) {
    int n = blockIdx.x;
    int t = threadIdx.x;  // 128 threads = output column
    int s = g_off[n], e_end = g_off[n + 1];
    float p = g_P[(size_t)n * 128 + t];
    float acc[8];
#pragma unroll
    for (int h = 0; h < 8; h++) acc[h] = 0.f;
    if (e_end > s) {
        for (int j = s; j < e_end; j++) {
            int e = g_perm[j];
            float m = lrelu(p + g_attrpart[(size_t)e * 128 + t]);
            const float4* xp = (const float4*)(g_ex + e * 8);
            float4 ea = xp[0], eb = xp[1];
            acc[0] += ea.x * m; acc[1] += ea.y * m; acc[2] += ea.z * m; acc[3] += ea.w * m;
            acc[4] += eb.x * m; acc[5] += eb.y * m; acc[6] += eb.z * m; acc[7] += eb.w * m;
        }
        const float4* dp = (const float4*)(g_denom + n * 8);
        float4 da = dp[0], db = dp[1];
        acc[0] /= da.x; acc[1] /= da.y; acc[2] /= da.z; acc[3] /= da.w;
        acc[4] /= db.x; acc[5] /= db.y; acc[6] /= db.z; acc[7] /= db.w;
    }
#pragma unroll
    for (int h = 0; h < 8; h++) out[(size_t)n * 1024 + h * 128 + t] = acc[h];
}

// ---------------- launch ----------------
extern "C" void kernel_launch(void* const* d_in, const int* in_sizes, int n_in,
                              void* d_out, int out_size) {
    const float* node_feats = (const float*)d_in[0];
    const int*   edge_index = (const int*)d_in[1];
    const float* edge_attr  = (const float*)d_in[2];
    const float* edge_type  = (const float*)d_in[3];
    const int*   ntl        = (const int*)d_in[4];
    const float* W_node  = (const float*)d_in[6];
    const float* W_eattr = (const float*)d_in[7];
    const float* W_etype = (const float*)d_in[8];
    const float* W_upd   = (const float*)d_in[9];
    const float* W_attn  = (const float*)d_in[10];
    float* out = (float*)d_out;

    cudaFuncSetAttribute(k_edge, cudaFuncAttributeMaxDynamicSharedMemorySize, EDGE_SMEM_BYTES);
    cudaFuncSetAttribute(k_node, cudaFuncAttributeMaxDynamicSharedMemorySize, NODE_SMEM_BYTES);

    const int TB = 256;
    const int GB_E = (N_EDGES + TB - 1) / TB;

    k_init<<<GB_E, TB>>>(edge_index);
    k_hist<<<GB_E, TB>>>();
    k_scan<<<1, 1024>>>();
    k_scatter<<<GB_E, TB>>>();
    k_node<<<(N_NODES + 31) / 32, 256, NODE_SMEM_BYTES>>>(node_feats, ntl, W_node, W_upd, W_attn);
    k_edge<<<148, ETHREADS, EDGE_SMEM_BYTES>>>(edge_attr, edge_type, W_eattr, W_etype, W_upd, W_attn);
    k_aggr<<<N_NODES, 128>>>(out);
}

// round 4
// speedup vs baseline: 1.4550x; 1.4550x over previous
#include <cuda_runtime.h>
#include <math.h>

#define N_NODES 50000
#define N_EDGES 400000
#define SLOPE   0.2f

typedef unsigned long long u64;

__device__ __forceinline__ u64 ffma2(u64 a, u64 b, u64 c) {
    u64 d;
    asm("fma.rn.f32x2 %0, %1, %2, %3;" : "=l"(d) : "l"(a), "l"(b), "l"(c));
    return d;
}
__device__ __forceinline__ u64 splat2(float x) {
    u64 d;
    unsigned xi = __float_as_uint(x);
    asm("mov.b64 %0, {%1, %1};" : "=l"(d) : "r"(xi));
    return d;
}
__device__ __forceinline__ float2 unpack2(u64 v) {
    float2 r;
    asm("mov.b64 {%0, %1}, %2;" : "=f"(r.x), "=f"(r.y) : "l"(v));
    return r;
}

// ---------------- scratch ----------------
__device__ __align__(16) float g_P[(size_t)N_NODES * 128];
__device__ __align__(16) float g_star[N_NODES * 8];
__device__ __align__(16) float g_ssrc[N_NODES * 8];
__device__ __align__(16) float g_attrpart[(size_t)N_EDGES * 128];
__device__ __align__(16) float g_ex[N_EDGES * 8];
__device__ __align__(16) float g_denom[N_NODES * 8];
__device__ int g_src[N_EDGES], g_tar[N_EDGES];
__device__ int g_deg[N_NODES], g_off[N_NODES + 1], g_cursor[N_NODES], g_perm[N_EDGES];

__device__ __forceinline__ float lrelu(float x) { return x >= 0.f ? x : SLOPE * x; }

// ---------------- init (indices are INT32) ----------------
__global__ void k_init(const int* __restrict__ eidx) {
    int i = blockIdx.x * blockDim.x + threadIdx.x;
    if (i < N_EDGES) {
        g_src[i] = eidx[i];
        g_tar[i] = eidx[N_EDGES + i];
    }
    if (i < N_NODES * 8) g_denom[i] = 0.f;
    if (i < N_NODES) g_deg[i] = 0;
}

__global__ void k_hist() {
    int i = blockIdx.x * blockDim.x + threadIdx.x;
    if (i < N_EDGES) atomicAdd(&g_deg[g_src[i]], 1);
}

__global__ void k_scan() {
    __shared__ int s[1024];
    const int CH = (N_NODES + 1023) / 1024;
    int t = threadIdx.x;
    int base = t * CH;
    int sum = 0;
    for (int i = 0; i < CH; i++) {
        int idx = base + i;
        if (idx < N_NODES) sum += g_deg[idx];
    }
    s[t] = sum;
    __syncthreads();
    for (int d = 1; d < 1024; d <<= 1) {
        int v = (t >= d) ? s[t - d] : 0;
        __syncthreads();
        s[t] += v;
        __syncthreads();
    }
    int run = (t == 0) ? 0 : s[t - 1];
    for (int i = 0; i < CH; i++) {
        int idx = base + i;
        if (idx < N_NODES) {
            g_off[idx] = run;
            g_cursor[idx] = run;
            run += g_deg[idx];
        }
    }
    if (t == 1023) g_off[N_NODES] = N_EDGES;
}

__global__ void k_scatter() {
    int i = blockIdx.x * blockDim.x + threadIdx.x;
    if (i < N_EDGES) {
        int p = atomicAdd(&g_cursor[g_src[i]], 1);
        g_perm[p] = i;
    }
}

// ---------------- merged node kernel ----------------
#define NODE_SMEM_BYTES ((8192 + 4224) * 4)

__global__ void k_node(const float* __restrict__ x, const int* __restrict__ ntl,
                       const float* __restrict__ Wn, const float* __restrict__ Wupd,
                       const float* __restrict__ Wattn) {
    extern __shared__ float smn[];
    float* sx = smn;          // 32 x 256
    float* se = smn + 8192;   // 32 x 132
    int n0 = blockIdx.x * 32;
    int t = threadIdx.x;

    for (int i = t; i < 2048; i += 256) {
        int row = i >> 6, c4 = i & 63;
        int node = n0 + row;
        float4 v = make_float4(0.f, 0.f, 0.f, 0.f);
        if (node < N_NODES) v = ((const float4*)(x + (size_t)node * 256))[c4];
        ((float4*)sx)[row * 64 + c4] = v;
    }
    __syncthreads();

    int tx = t & 31, ty = t >> 5;
    int r0 = ty * 4;

    // emb = x @ W_node[type]  (scalar FFMA: 4 distinct global weight streams)
    {
        const float* wp[4];
#pragma unroll
        for (int j = 0; j < 4; j++) {
            int node = n0 + r0 + j;
            int tp = (node < N_NODES) ? ntl[node] : 0;
            wp[j] = Wn + (size_t)tp * (256 * 128) + tx * 4;
        }
        float acc[4][4];
#pragma unroll
        for (int j = 0; j < 4; j++)
#pragma unroll
            for (int c = 0; c < 4; c++) acc[j][c] = 0.f;
#pragma unroll 4
        for (int k = 0; k < 256; k++) {
#pragma unroll
            for (int j = 0; j < 4; j++) {
                float4 w = *(const float4*)(wp[j] + (size_t)k * 128);
                float xv = sx[(r0 + j) * 256 + k];
                acc[j][0] += xv * w.x; acc[j][1] += xv * w.y;
                acc[j][2] += xv * w.z; acc[j][3] += xv * w.w;
            }
        }
#pragma unroll
        for (int j = 0; j < 4; j++)
            *(float4*)(se + (r0 + j) * 132 + tx * 4) =
                make_float4(acc[j][0], acc[j][1], acc[j][2], acc[j][3]);
    }
    __syncthreads();

    // P = emb @ W_upd[0:128]  (f32x2)
    {
        u64 a01[4], a23[4];
#pragma unroll
        for (int j = 0; j < 4; j++) { a01[j] = 0ull; a23[j] = 0ull; }
#pragma unroll 4
        for (int k = 0; k < 128; k++) {
            const float* wr = Wupd + (size_t)k * 128 + tx * 4;
            float4 w = *(const float4*)wr;
            u64 w01, w23;
            asm("mov.b64 %0, {%1, %2};" : "=l"(w01) : "f"(w.x), "f"(w.y));
            asm("mov.b64 %0, {%1, %2};" : "=l"(w23) : "f"(w.z), "f"(w.w));
#pragma unroll
            for (int j = 0; j < 4; j++) {
                u64 xs = splat2(se[(r0 + j) * 132 + k]);
                a01[j] = ffma2(xs, w01, a01[j]);
                a23[j] = ffma2(xs, w23, a23[j]);
            }
        }
#pragma unroll
        for (int j = 0; j < 4; j++) {
            int node = n0 + r0 + j;
            if (node < N_NODES) {
                float2 c01 = unpack2(a01[j]), c23 = unpack2(a23[j]);
                *(float4*)(g_P + (size_t)node * 128 + tx * 4) =
                    make_float4(c01.x, c01.y, c23.x, c23.y);
            }
        }
    }

    // s_tar / s_src
    {
        int e = t >> 3, h = t & 7;
        int node = n0 + e;
        float at = 0.f, as = 0.f;
        for (int k = 0; k < 128; k++) {
            float v = se[e * 132 + k];
            at += v * Wattn[k * 8 + h];
            as += v * Wattn[(384 + k) * 8 + h];
        }
        if (node < N_NODES) {
            g_star[node * 8 + h] = at;
            g_ssrc[node * 8 + h] = as;
        }
    }
}

// ---------------- fused edge kernel (round-2 tiling, f32x2 math) ----------------
// dynamic smem layout (floats): Xa[2048] Xt[2048] A[32*132] T[32*132] Wa[2112] W[8192]
#define SM_XA 0
#define SM_XT 2048
#define SM_A  4096
#define SM_T  8320
#define SM_WA 12544
#define SM_W  14656
#define EDGE_SMEM_FLOATS (14656 + 8192)
#define EDGE_SMEM_BYTES  (EDGE_SMEM_FLOATS * 4)

__global__ void k_edge(const float* __restrict__ eattr, const float* __restrict__ etype,
                       const float* __restrict__ Weattr, const float* __restrict__ Wetype,
                       const float* __restrict__ Wupd, const float* __restrict__ Wattn) {
    extern __shared__ float sm[];
    __shared__ int sSrc[32], sTar[32];
    float* Xa = sm + SM_XA;
    float* Xt = sm + SM_XT;
    float* A  = sm + SM_A;   // 32 x 132
    float* T  = sm + SM_T;   // 32 x 132
    float* Wa = sm + SM_WA;  // transposed W_attn[128:384]: [8][264]
    float* W  = sm + SM_W;   // 64 x 128 staging

    int e0 = blockIdx.x * 32;
    int t = threadIdx.x;

    for (int i = t; i < 512; i += 256) {
        ((float4*)Xa)[i] = ((const float4*)(eattr + (size_t)e0 * 64))[i];
        ((float4*)Xt)[i] = ((const float4*)(etype + (size_t)e0 * 64))[i];
    }
    for (int i = t; i < 2048; i += 256) {
        int k = i >> 3, h = i & 7;
        Wa[h * 264 + k] = Wattn[(128 + k) * 8 + h];
    }
    for (int i = t; i < 2048; i += 256) ((float4*)W)[i] = ((const float4*)Weattr)[i];
    if (t < 32) { sSrc[t] = g_src[e0 + t]; sTar[t] = g_tar[e0 + t]; }
    __syncthreads();

    int tx = t & 31, ty = t >> 5;
    int r0 = ty * 4;

    // phase A: A = lrelu(Xa @ W_eattr)
    {
        u64 a01[4], a23[4];
#pragma unroll
        for (int j = 0; j < 4; j++) { a01[j] = 0ull; a23[j] = 0ull; }
#pragma unroll 4
        for (int k = 0; k < 64; k++) {
            const float* wr = W + k * 128 + tx * 4;
            u64 w01 = *(const u64*)wr;
            u64 w23 = *(const u64*)(wr + 2);
#pragma unroll
            for (int j = 0; j < 4; j++) {
                u64 xs = splat2(Xa[(r0 + j) * 64 + k]);
                a01[j] = ffma2(xs, w01, a01[j]);
                a23[j] = ffma2(xs, w23, a23[j]);
            }
        }
#pragma unroll
        for (int j = 0; j < 4; j++) {
            float2 c01 = unpack2(a01[j]), c23 = unpack2(a23[j]);
            *(float4*)(A + (r0 + j) * 132 + tx * 4) =
                make_float4(lrelu(c01.x), lrelu(c01.y), lrelu(c23.x), lrelu(c23.y));
        }
    }
    __syncthreads();
    for (int i = t; i < 2048; i += 256) ((float4*)W)[i] = ((const float4*)Wetype)[i];
    __syncthreads();

    // phase T: T = lrelu(Xt @ W_etype)
    {
        u64 a01[4], a23[4];
#pragma unroll
        for (int j = 0; j < 4; j++) { a01[j] = 0ull; a23[j] = 0ull; }
#pragma unroll 4
        for (int k = 0; k < 64; k++) {
            const float* wr = W + k * 128 + tx * 4;
            u64 w01 = *(const u64*)wr;
            u64 w23 = *(const u64*)(wr + 2);
#pragma unroll
            for (int j = 0; j < 4; j++) {
                u64 xs = splat2(Xt[(r0 + j) * 64 + k]);
                a01[j] = ffma2(xs, w01, a01[j]);
                a23[j] = ffma2(xs, w23, a23[j]);
            }
        }
#pragma unroll
        for (int j = 0; j < 4; j++) {
            float2 c01 = unpack2(a01[j]), c23 = unpack2(a23[j]);
            *(float4*)(T + (r0 + j) * 132 + tx * 4) =
                make_float4(lrelu(c01.x), lrelu(c01.y), lrelu(c23.x), lrelu(c23.y));
        }
    }
    __syncthreads();

    // phase P: attrpart = A @ W_upd[128:256] (two 64-row halves of Wupd staged)
    u64 p01[4], p23[4];
#pragma unroll
    for (int j = 0; j < 4; j++) { p01[j] = 0ull; p23[j] = 0ull; }

    for (int i = t; i < 2048; i += 256) ((float4*)W)[i] = ((const float4*)Wupd)[4096 + i];
    __syncthreads();
#pragma unroll 4
    for (int k = 0; k < 64; k++) {
        const float* wr = W + k * 128 + tx * 4;
        u64 w01 = *(const u64*)wr;
        u64 w23 = *(const u64*)(wr + 2);
#pragma unroll
        for (int j = 0; j < 4; j++) {
            u64 xs = splat2(A[(r0 + j) * 132 + k]);
            p01[j] = ffma2(xs, w01, p01[j]);
            p23[j] = ffma2(xs, w23, p23[j]);
        }
    }
    __syncthreads();
    for (int i = t; i < 2048; i += 256) ((float4*)W)[i] = ((const float4*)Wupd)[6144 + i];
    __syncthreads();
#pragma unroll 4
    for (int k = 0; k < 64; k++) {
        const float* wr = W + k * 128 + tx * 4;
        u64 w01 = *(const u64*)wr;
        u64 w23 = *(const u64*)(wr + 2);
#pragma unroll
        for (int j = 0; j < 4; j++) {
            u64 xs = splat2(A[(r0 + j) * 132 + 64 + k]);
            p01[j] = ffma2(xs, w01, p01[j]);
            p23[j] = ffma2(xs, w23, p23[j]);
        }
    }
#pragma unroll
    for (int j = 0; j < 4; j++) {
        float2 c01 = unpack2(p01[j]), c23 = unpack2(p23[j]);
        *(float4*)(g_attrpart + (size_t)(e0 + r0 + j) * 128 + tx * 4) =
            make_float4(c01.x, c01.y, c23.x, c23.y);
    }

    // scores: one thread per (edge, head), f32x2 dot
    {
        int e = t >> 3, h = t & 7;
        int src = sSrc[e], tar = sTar[e];
        float sc = g_star[tar * 8 + h] + g_ssrc[src * 8 + h];
        u64 s01 = 0ull, s23 = 0ull;
        const float* ar = A + e * 132;
        const float* tr = T + e * 132;
        const float* wr = Wa + h * 264;
#pragma unroll 4
        for (int k = 0; k < 128; k += 4) {
            u64 a0 = *(const u64*)(ar + k);
            u64 a1 = *(const u64*)(ar + k + 2);
            u64 w0 = *(const u64*)(wr + k);
            u64 w1 = *(const u64*)(wr + k + 2);
            s01 = ffma2(a0, w0, s01);
            s23 = ffma2(a1, w1, s23);
            u64 t0 = *(const u64*)(tr + k);
            u64 t1 = *(const u64*)(tr + k + 2);
            u64 v0 = *(const u64*)(wr + 128 + k);
            u64 v1 = *(const u64*)(wr + 128 + k + 2);
            s01 = ffma2(t0, v0, s01);
            s23 = ffma2(t1, v1, s23);
        }
        float2 f01 = unpack2(s01), f23 = unpack2(s23);
        sc += (f01.x + f01.y) + (f23.x + f23.y);
        sc = lrelu(sc);
        float ex = expf(sc);
        g_ex[(e0 + e) * 8 + h] = ex;
        atomicAdd(&g_denom[src * 8 + h], ex);
    }
}

// ---------------- aggregation (f32x2 head MACs) ----------------
__global__ void k_aggr(float* __restrict__ out) {
    int n = blockIdx.x;
    int t = threadIdx.x;  // 128 threads = output column
    int s = g_off[n], e_end = g_off[n + 1];
    float p = g_P[(size_t)n * 128 + t];
    u64 acc[4];
#pragma unroll
    for (int h = 0; h < 4; h++) acc[h] = 0ull;
    float res[8];
#pragma unroll
    for (int h = 0; h < 8; h++) res[h] = 0.f;
    if (e_end > s) {
        for (int j = s; j < e_end; j++) {
            int e = g_perm[j];
            float m = lrelu(p + g_attrpart[(size_t)e * 128 + t]);
            u64 m2 = splat2(m);
            ulonglong2 ea = *(const ulonglong2*)(g_ex + e * 8);
            ulonglong2 eb = *(const ulonglong2*)(g_ex + e * 8 + 4);
            acc[0] = ffma2(m2, ea.x, acc[0]);
            acc[1] = ffma2(m2, ea.y, acc[1]);
            acc[2] = ffma2(m2, eb.x, acc[2]);
            acc[3] = ffma2(m2, eb.y, acc[3]);
        }
        const float4* dp = (const float4*)(g_denom + n * 8);
        float4 da = dp[0], db = dp[1];
        float2 a0 = unpack2(acc[0]), a1 = unpack2(acc[1]);
        float2 a2 = unpack2(acc[2]), a3 = unpack2(acc[3]);
        res[0] = a0.x / da.x; res[1] = a0.y / da.y;
        res[2] = a1.x / da.z; res[3] = a1.y / da.w;
        res[4] = a2.x / db.x; res[5] = a2.y / db.y;
        res[6] = a3.x / db.z; res[7] = a3.y / db.w;
    }
#pragma unroll
    for (int h = 0; h < 8; h++) out[(size_t)n * 1024 + h * 128 + t] = res[h];
}

// ---------------- launch ----------------
extern "C" void kernel_launch(void* const* d_in, const int* in_sizes, int n_in,
                              void* d_out, int out_size) {
    const float* node_feats = (const float*)d_in[0];
    const int*   edge_index = (const int*)d_in[1];
    const float* edge_attr  = (const float*)d_in[2];
    const float* edge_type  = (const float*)d_in[3];
    const int*   ntl        = (const int*)d_in[4];
    const float* W_node  = (const float*)d_in[6];
    const float* W_eattr = (const float*)d_in[7];
    const float* W_etype = (const float*)d_in[8];
    const float* W_upd   = (const float*)d_in[9];
    const float* W_attn  = (const float*)d_in[10];
    float* out = (float*)d_out;

    cudaFuncSetAttribute(k_edge, cudaFuncAttributeMaxDynamicSharedMemorySize, EDGE_SMEM_BYTES);
    cudaFuncSetAttribute(k_node, cudaFuncAttributeMaxDynamicSharedMemorySize, NODE_SMEM_BYTES);

    const int TB = 256;
    const int GB_E = (N_EDGES + TB - 1) / TB;

    k_init<<<GB_E, TB>>>(edge_index);
    k_hist<<<GB_E, TB>>>();
    k_scan<<<1, 1024>>>();
    k_scatter<<<GB_E, TB>>>();
    k_node<<<(N_NODES + 31) / 32, 256, NODE_SMEM_BYTES>>>(node_feats, ntl, W_node, W_upd, W_attn);
    k_edge<<<N_EDGES / 32, 256, EDGE_SMEM_BYTES>>>(edge_attr, edge_type, W_eattr, W_etype, W_upd, W_attn);
    k_aggr<<<N_NODES, 128>>>(out);
}

// round 5
// speedup vs baseline: 1.5820x; 1.0872x over previous
#include <cuda_runtime.h>
#include <cuda_bf16.h>
#include <math.h>

#define N_NODES 50000
#define N_EDGES 400000
#define SLOPE   0.2f

#define ETILE   64
#define NTILES  (N_EDGES / ETILE)   // 6250, exact

// ---------------- scratch ----------------
__device__ __align__(16) float g_P[(size_t)N_NODES * 128];
__device__ __align__(16) float g_star[N_NODES * 8];
__device__ __align__(16) float g_ssrc[N_NODES * 8];
__device__ __align__(16) float g_attrpart[(size_t)N_EDGES * 128];
__device__ __align__(16) float g_ex[N_EDGES * 8];
__device__ __align__(16) float g_denom[N_NODES * 8];
__device__ int g_src[N_EDGES], g_tar[N_EDGES];
__device__ int g_deg[N_NODES], g_off[N_NODES + 1], g_cursor[N_NODES], g_perm[N_EDGES];

// prepped split-bf16 transposed weights  [n][k]
__device__ __align__(16) __nv_bfloat16 gWeaHiT[128 * 64],  gWeaLoT[128 * 64];
__device__ __align__(16) __nv_bfloat16 gWetHiT[128 * 64],  gWetLoT[128 * 64];
__device__ __align__(16) __nv_bfloat16 gWupHiT[128 * 128], gWupLoT[128 * 128];
__device__ __align__(16) __nv_bfloat16 gWaHiT[8 * 256],    gWaLoT[8 * 256];

__device__ __forceinline__ float lrelu(float x) { return x >= 0.f ? x : SLOPE * x; }

__device__ __forceinline__ void splitpack(float x, float y, unsigned& hi, unsigned& lo) {
    __nv_bfloat16 hx = __float2bfloat16(x);
    __nv_bfloat16 hy = __float2bfloat16(y);
    float lx = x - __bfloat162float(hx);
    float ly = y - __bfloat162float(hy);
    __nv_bfloat162 h2 = __halves2bfloat162(hx, hy);
    __nv_bfloat162 l2 = __halves2bfloat162(__float2bfloat16(lx), __float2bfloat16(ly));
    hi = *reinterpret_cast<unsigned*>(&h2);
    lo = *reinterpret_cast<unsigned*>(&l2);
}

__device__ __forceinline__ void mma16816(float* c, unsigned a0, unsigned a1, unsigned a2,
                                         unsigned a3, unsigned b0, unsigned b1) {
    asm volatile(
        "mma.sync.aligned.m16n8k16.row.col.f32.bf16.bf16.f32 "
        "{%0,%1,%2,%3}, {%4,%5,%6,%7}, {%8,%9}, {%0,%1,%2,%3};"
        : "+f"(c[0]), "+f"(c[1]), "+f"(c[2]), "+f"(c[3])
        : "r"(a0), "r"(a1), "r"(a2), "r"(a3), "r"(b0), "r"(b1));
}

// ---------------- weight prep: split + transpose ----------------
__global__ void k_wprep(const float* __restrict__ Wea, const float* __restrict__ Wet,
                        const float* __restrict__ Wupd, const float* __restrict__ Wattn) {
    int i = blockIdx.x * blockDim.x + threadIdx.x;
    if (i < 8192) {                                   // [n=128][k=64]
        int n = i >> 6, k = i & 63;
        float x = Wea[k * 128 + n];
        __nv_bfloat16 h = __float2bfloat16(x);
        gWeaHiT[i] = h; gWeaLoT[i] = __float2bfloat16(x - __bfloat162float(h));
        x = Wet[k * 128 + n];
        h = __float2bfloat16(x);
        gWetHiT[i] = h; gWetLoT[i] = __float2bfloat16(x - __bfloat162float(h));
    }
    if (i < 16384) {                                  // [n=128][k=128], W_upd rows 128..255
        int n = i >> 7, k = i & 127;
        float x = Wupd[(128 + k) * 128 + n];
        __nv_bfloat16 h = __float2bfloat16(x);
        gWupHiT[i] = h; gWupLoT[i] = __float2bfloat16(x - __bfloat162float(h));
    }
    if (i < 2048) {                                   // [h=8][k=256], W_attn rows 128..383
        int hh = i >> 8, k = i & 255;
        float x = Wattn[(128 + k) * 8 + hh];
        __nv_bfloat16 h = __float2bfloat16(x);
        gWaHiT[i] = h; gWaLoT[i] = __float2bfloat16(x - __bfloat162float(h));
    }
}

// ---------------- init (indices are INT32) ----------------
__global__ void k_init(const int* __restrict__ eidx) {
    int i = blockIdx.x * blockDim.x + threadIdx.x;
    if (i < N_EDGES) {
        g_src[i] = eidx[i];
        g_tar[i] = eidx[N_EDGES + i];
    }
    if (i < N_NODES * 8) g_denom[i] = 0.f;
    if (i < N_NODES) g_deg[i] = 0;
}

__global__ void k_hist() {
    int i = blockIdx.x * blockDim.x + threadIdx.x;
    if (i < N_EDGES) atomicAdd(&g_deg[g_src[i]], 1);
}

__global__ void k_scan() {
    __shared__ int s[1024];
    const int CH = (N_NODES + 1023) / 1024;
    int t = threadIdx.x;
    int base = t * CH;
    int sum = 0;
    for (int i = 0; i < CH; i++) {
        int idx = base + i;
        if (idx < N_NODES) sum += g_deg[idx];
    }
    s[t] = sum;
    __syncthreads();
    for (int d = 1; d < 1024; d <<= 1) {
        int v = (t >= d) ? s[t - d] : 0;
        __syncthreads();
        s[t] += v;
        __syncthreads();
    }
    int run = (t == 0) ? 0 : s[t - 1];
    for (int i = 0; i < CH; i++) {
        int idx = base + i;
        if (idx < N_NODES) {
            g_off[idx] = run;
            g_cursor[idx] = run;
            run += g_deg[idx];
        }
    }
    if (t == 1023) g_off[N_NODES] = N_EDGES;
}

__global__ void k_scatter() {
    int i = blockIdx.x * blockDim.x + threadIdx.x;
    if (i < N_EDGES) {
        int p = atomicAdd(&g_cursor[g_src[i]], 1);
        g_perm[p] = i;
    }
}

// ---------------- merged node kernel (fp32, round-2 proven) ----------------
#define NODE_SMEM_BYTES ((8192 + 4224) * 4)

__global__ void k_node(const float* __restrict__ x, const int* __restrict__ ntl,
                       const float* __restrict__ Wn, const float* __restrict__ Wupd,
                       const float* __restrict__ Wattn) {
    extern __shared__ float smn[];
    float* sx = smn;          // 32 x 256
    float* se = smn + 8192;   // 32 x 132
    int n0 = blockIdx.x * 32;
    int t = threadIdx.x;

    for (int i = t; i < 2048; i += 256) {
        int row = i >> 6, c4 = i & 63;
        int node = n0 + row;
        float4 v = make_float4(0.f, 0.f, 0.f, 0.f);
        if (node < N_NODES) v = ((const float4*)(x + (size_t)node * 256))[c4];
        ((float4*)sx)[row * 64 + c4] = v;
    }
    __syncthreads();

    int tx = t & 31, ty = t >> 5;
    int r0 = ty * 4;

    {   // emb = x @ W_node[type]
        const float* wp[4];
#pragma unroll
        for (int j = 0; j < 4; j++) {
            int node = n0 + r0 + j;
            int tp = (node < N_NODES) ? ntl[node] : 0;
            wp[j] = Wn + (size_t)tp * (256 * 128) + tx * 4;
        }
        float acc[4][4];
#pragma unroll
        for (int j = 0; j < 4; j++)
#pragma unroll
            for (int c = 0; c < 4; c++) acc[j][c] = 0.f;
#pragma unroll 4
        for (int k = 0; k < 256; k++) {
#pragma unroll
            for (int j = 0; j < 4; j++) {
                float4 w = *(const float4*)(wp[j] + (size_t)k * 128);
                float xv = sx[(r0 + j) * 256 + k];
                acc[j][0] += xv * w.x; acc[j][1] += xv * w.y;
                acc[j][2] += xv * w.z; acc[j][3] += xv * w.w;
            }
        }
#pragma unroll
        for (int j = 0; j < 4; j++)
            *(float4*)(se + (r0 + j) * 132 + tx * 4) =
                make_float4(acc[j][0], acc[j][1], acc[j][2], acc[j][3]);
    }
    __syncthreads();

    {   // P = emb @ W_upd[0:128]
        float acc[4][4];
#pragma unroll
        for (int j = 0; j < 4; j++)
#pragma unroll
            for (int c = 0; c < 4; c++) acc[j][c] = 0.f;
#pragma unroll 4
        for (int k = 0; k < 128; k++) {
            float4 w = *(const float4*)(Wupd + (size_t)k * 128 + tx * 4);
#pragma unroll
            for (int j = 0; j < 4; j++) {
                float xv = se[(r0 + j) * 132 + k];
                acc[j][0] += xv * w.x; acc[j][1] += xv * w.y;
                acc[j][2] += xv * w.z; acc[j][3] += xv * w.w;
            }
        }
#pragma unroll
        for (int j = 0; j < 4; j++) {
            int node = n0 + r0 + j;
            if (node < N_NODES)
                *(float4*)(g_P + (size_t)node * 128 + tx * 4) =
                    make_float4(acc[j][0], acc[j][1], acc[j][2], acc[j][3]);
        }
    }

    {   // s_tar / s_src
        int e = t >> 3, h = t & 7;
        int node = n0 + e;
        float at = 0.f, as = 0.f;
        for (int k = 0; k < 128; k++) {
            float v = se[e * 132 + k];
            at += v * Wattn[k * 8 + h];
            as += v * Wattn[(384 + k) * 8 + h];
        }
        if (node < N_NODES) {
            g_star[node * 8 + h] = at;
            g_ssrc[node * 8 + h] = as;
        }
    }
}

// ---------------- tensor-core edge kernel ----------------
// dynamic smem (u32 units): Xhi[64*36] Xlo[64*36] Ahi[64*68] Alo Thi Tlo
#define XHI 0
#define XLO 2304
#define AHI 4608
#define ALO 8960
#define THI 13312
#define TLO 17664
#define EDGE_SMEM_U32 22016
#define EDGE_SMEM_BYTES (EDGE_SMEM_U32 * 4)

// one warp's GEMM: acc[8][4] += Op(64 x K)[rows rb..rb+15] @ W(K x 128)[cols nh*64..+63]
// xh/xl: smem u32 base (STRIDE u32 per row). WhT/WlT: [n][k] bf16 as u32, wk u32/row.
template <int KSTEPS, int STRIDE>
__device__ __forceinline__ void gemm_frag(const unsigned* xh, const unsigned* xl,
                                          const unsigned* WhT, const unsigned* WlT,
                                          int wk, int rb, int nh, int lane,
                                          float acc[8][4]) {
    int fr = lane >> 2, fc = lane & 3;
#pragma unroll
    for (int kk = 0; kk < KSTEPS; kk++) {
        int o0 = (rb + fr) * STRIDE + kk * 8 + fc;
        int o1 = (rb + fr + 8) * STRIDE + kk * 8 + fc;
        unsigned ah0 = xh[o0], ah1 = xh[o1], ah2 = xh[o0 + 4], ah3 = xh[o1 + 4];
        unsigned al0 = xl[o0], al1 = xl[o1], al2 = xl[o0 + 4], al3 = xl[o1 + 4];
#pragma unroll
        for (int j = 0; j < 8; j++) {
            int n = nh * 64 + j * 8 + fr;
            const unsigned* wh = WhT + n * wk + kk * 8 + fc;
            const unsigned* wl = WlT + n * wk + kk * 8 + fc;
            unsigned bh0 = wh[0], bh1 = wh[4];
            unsigned bl0 = wl[0], bl1 = wl[4];
            mma16816(acc[j], ah0, ah1, ah2, ah3, bh0, bh1);
            mma16816(acc[j], ah0, ah1, ah2, ah3, bl0, bl1);
            mma16816(acc[j], al0, al1, al2, al3, bh0, bh1);
        }
    }
}

__global__ void __launch_bounds__(256)
k_edge(const float* __restrict__ eattr, const float* __restrict__ etype) {
    extern __shared__ unsigned su[];
    __shared__ int sSrc[ETILE], sTar[ETILE];

    int t = threadIdx.x, lane = t & 31, w = t >> 5;
    int rt = w >> 1, nh = w & 1;
    int rb = rt * 16;
    int fr = lane >> 2, fc = lane & 3;
    int e0 = blockIdx.x * ETILE;

    const unsigned* WeaH = (const unsigned*)gWeaHiT;
    const unsigned* WeaL = (const unsigned*)gWeaLoT;
    const unsigned* WetH = (const unsigned*)gWetHiT;
    const unsigned* WetL = (const unsigned*)gWetLoT;
    const unsigned* WupH = (const unsigned*)gWupHiT;
    const unsigned* WupL = (const unsigned*)gWupLoT;
    const unsigned* WaH  = (const unsigned*)gWaHiT;
    const unsigned* WaL  = (const unsigned*)gWaLoT;

    // ---- stage Xa (split to bf16 hi/lo) ----
    {
        int row = t >> 2, cg = (t & 3) * 16;
        const float4* src = (const float4*)(eattr + (size_t)(e0 + row) * 64 + cg);
        unsigned* xh = su + XHI + row * 36 + cg / 2;
        unsigned* xl = su + XLO + row * 36 + cg / 2;
#pragma unroll
        for (int p = 0; p < 4; p++) {
            float4 v = src[p];
            unsigned h0, l0, h1, l1;
            splitpack(v.x, v.y, h0, l0);
            splitpack(v.z, v.w, h1, l1);
            xh[p * 2] = h0; xh[p * 2 + 1] = h1;
            xl[p * 2] = l0; xl[p * 2 + 1] = l1;
        }
    }
    if (t < ETILE) sSrc[t] = g_src[e0 + t];
    else if (t < 2 * ETILE) sTar[t - ETILE] = g_tar[e0 + t - ETILE];
    __syncthreads();

    float acc[8][4];

    // ---- phase A: A = lrelu(Xa @ Wea) ----
#pragma unroll
    for (int j = 0; j < 8; j++)
#pragma unroll
        for (int c = 0; c < 4; c++) acc[j][c] = 0.f;
    gemm_frag<4, 36>(su + XHI, su + XLO, WeaH, WeaL, 32, rb, nh, lane, acc);
#pragma unroll
    for (int j = 0; j < 8; j++) {
        int colu = nh * 32 + j * 4 + fc;
        unsigned h, l;
        splitpack(lrelu(acc[j][0]), lrelu(acc[j][1]), h, l);
        su[AHI + (rb + fr) * 68 + colu] = h;
        su[ALO + (rb + fr) * 68 + colu] = l;
        splitpack(lrelu(acc[j][2]), lrelu(acc[j][3]), h, l);
        su[AHI + (rb + fr + 8) * 68 + colu] = h;
        su[ALO + (rb + fr + 8) * 68 + colu] = l;
    }
    __syncthreads();

    // ---- stage Xt ----
    {
        int row = t >> 2, cg = (t & 3) * 16;
        const float4* src = (const float4*)(etype + (size_t)(e0 + row) * 64 + cg);
        unsigned* xh = su + XHI + row * 36 + cg / 2;
        unsigned* xl = su + XLO + row * 36 + cg / 2;
#pragma unroll
        for (int p = 0; p < 4; p++) {
            float4 v = src[p];
            unsigned h0, l0, h1, l1;
            splitpack(v.x, v.y, h0, l0);
            splitpack(v.z, v.w, h1, l1);
            xh[p * 2] = h0; xh[p * 2 + 1] = h1;
            xl[p * 2] = l0; xl[p * 2 + 1] = l1;
        }
    }
    __syncthreads();

    // ---- phase T: T = lrelu(Xt @ Wet) ----
#pragma unroll
    for (int j = 0; j < 8; j++)
#pragma unroll
        for (int c = 0; c < 4; c++) acc[j][c] = 0.f;
    gemm_frag<4, 36>(su + XHI, su + XLO, WetH, WetL, 32, rb, nh, lane, acc);
#pragma unroll
    for (int j = 0; j < 8; j++) {
        int colu = nh * 32 + j * 4 + fc;
        unsigned h, l;
        splitpack(lrelu(acc[j][0]), lrelu(acc[j][1]), h, l);
        su[THI + (rb + fr) * 68 + colu] = h;
        su[TLO + (rb + fr) * 68 + colu] = l;
        splitpack(lrelu(acc[j][2]), lrelu(acc[j][3]), h, l);
        su[THI + (rb + fr + 8) * 68 + colu] = h;
        su[TLO + (rb + fr + 8) * 68 + colu] = l;
    }
    __syncthreads();

    // ---- scores (warps 0-3, tensor): D[64x8] = A@Wa1 + T@Wa2 ----
    if (w < 4) {
        int srb = w * 16;
        float sacc[4] = {0.f, 0.f, 0.f, 0.f};
#pragma unroll
        for (int kk = 0; kk < 8; kk++) {   // A part, k 0..127
            int o0 = (srb + fr) * 68 + kk * 8 + fc;
            int o1 = (srb + fr + 8) * 68 + kk * 8 + fc;
            unsigned ah0 = su[AHI + o0], ah1 = su[AHI + o1];
            unsigned ah2 = su[AHI + o0 + 4], ah3 = su[AHI + o1 + 4];
            unsigned al0 = su[ALO + o0], al1 = su[ALO + o1];
            unsigned al2 = su[ALO + o0 + 4], al3 = su[ALO + o1 + 4];
            const unsigned* wh = WaH + fr * 128 + kk * 8 + fc;
            const unsigned* wl = WaL + fr * 128 + kk * 8 + fc;
            unsigned bh0 = wh[0], bh1 = wh[4], bl0 = wl[0], bl1 = wl[4];
            mma16816(sacc, ah0, ah1, ah2, ah3, bh0, bh1);
            mma16816(sacc, ah0, ah1, ah2, ah3, bl0, bl1);
            mma16816(sacc, al0, al1, al2, al3, bh0, bh1);
        }
#pragma unroll
        for (int kk = 0; kk < 8; kk++) {   // T part, k 128..255
            int o0 = (srb + fr) * 68 + kk * 8 + fc;
            int o1 = (srb + fr + 8) * 68 + kk * 8 + fc;
            unsigned ah0 = su[THI + o0], ah1 = su[THI + o1];
            unsigned ah2 = su[THI + o0 + 4], ah3 = su[THI + o1 + 4];
            unsigned al0 = su[TLO + o0], al1 = su[TLO + o1];
            unsigned al2 = su[TLO + o0 + 4], al3 = su[TLO + o1 + 4];
            const unsigned* wh = WaH + fr * 128 + 64 + kk * 8 + fc;
            const unsigned* wl = WaL + fr * 128 + 64 + kk * 8 + fc;
            unsigned bh0 = wh[0], bh1 = wh[4], bl0 = wl[0], bl1 = wl[4];
            mma16816(sacc, ah0, ah1, ah2, ah3, bh0, bh1);
            mma16816(sacc, ah0, ah1, ah2, ah3, bl0, bl1);
            mma16816(sacc, al0, al1, al2, al3, bh0, bh1);
        }
        int h0 = fc * 2;
#pragma unroll
        for (int q = 0; q < 4; q++) {
            int row = srb + fr + (q >> 1) * 8;     // q=0,1 -> row; q=2,3 -> row+8
            int h = h0 + (q & 1);
            int sr = sSrc[row], tg = sTar[row];
            float sc = sacc[q] + g_star[tg * 8 + h] + g_ssrc[sr * 8 + h];
            sc = lrelu(sc);
            float ex = expf(sc);
            g_ex[(e0 + row) * 8 + h] = ex;
            atomicAdd(&g_denom[sr * 8 + h], ex);
        }
    }

    // ---- phase P: attrpart = A @ Wupd[128:256] ----
#pragma unroll
    for (int j = 0; j < 8; j++)
#pragma unroll
        for (int c = 0; c < 4; c++) acc[j][c] = 0.f;
    gemm_frag<8, 68>(su + AHI, su + ALO, WupH, WupL, 64, rb, nh, lane, acc);
#pragma unroll
    for (int j = 0; j < 8; j++) {
        int n0 = nh * 64 + j * 8 + fc * 2;
        *(float2*)(g_attrpart + (size_t)(e0 + rb + fr) * 128 + n0) =
            make_float2(acc[j][0], acc[j][1]);
        *(float2*)(g_attrpart + (size_t)(e0 + rb + fr + 8) * 128 + n0) =
            make_float2(acc[j][2], acc[j][3]);
    }
}

// ---------------- aggregation ----------------
__global__ void k_aggr(float* __restrict__ out) {
    int n = blockIdx.x;
    int t = threadIdx.x;
    int s = g_off[n], e_end = g_off[n + 1];
    float p = g_P[(size_t)n * 128 + t];
    float acc[8];
#pragma unroll
    for (int h = 0; h < 8; h++) acc[h] = 0.f;
    if (e_end > s) {
        for (int j = s; j < e_end; j++) {
            int e = g_perm[j];
            float m = lrelu(p + g_attrpart[(size_t)e * 128 + t]);
            const float4* xp = (const float4*)(g_ex + e * 8);
            float4 ea = xp[0], eb = xp[1];
            acc[0] += ea.x * m; acc[1] += ea.y * m; acc[2] += ea.z * m; acc[3] += ea.w * m;
            acc[4] += eb.x * m; acc[5] += eb.y * m; acc[6] += eb.z * m; acc[7] += eb.w * m;
        }
        const float4* dp = (const float4*)(g_denom + n * 8);
        float4 da = dp[0], db = dp[1];
        acc[0] /= da.x; acc[1] /= da.y; acc[2] /= da.z; acc[3] /= da.w;
        acc[4] /= db.x; acc[5] /= db.y; acc[6] /= db.z; acc[7] /= db.w;
    }
#pragma unroll
    for (int h = 0; h < 8; h++) out[(size_t)n * 1024 + h * 128 + t] = acc[h];
}

// ---------------- launch ----------------
extern "C" void kernel_launch(void* const* d_in, const int* in_sizes, int n_in,
                              void* d_out, int out_size) {
    const float* node_feats = (const float*)d_in[0];
    const int*   edge_index = (const int*)d_in[1];
    const float* edge_attr  = (const float*)d_in[2];
    const float* edge_type  = (const float*)d_in[3];
    const int*   ntl        = (const int*)d_in[4];
    const float* W_node  = (const float*)d_in[6];
    const float* W_eattr = (const float*)d_in[7];
    const float* W_etype = (const float*)d_in[8];
    const float* W_upd   = (const float*)d_in[9];
    const float* W_attn  = (const float*)d_in[10];
    float* out = (float*)d_out;

    cudaFuncSetAttribute(k_edge, cudaFuncAttributeMaxDynamicSharedMemorySize, EDGE_SMEM_BYTES);
    cudaFuncSetAttribute(k_node, cudaFuncAttributeMaxDynamicSharedMemorySize, NODE_SMEM_BYTES);

    const int TB = 256;
    const int GB_E = (N_EDGES + TB - 1) / TB;

    k_wprep<<<64, 256>>>(W_eattr, W_etype, W_upd, W_attn);
    k_init<<<GB_E, TB>>>(edge_index);
    k_hist<<<GB_E, TB>>>();
    k_scan<<<1, 1024>>>();
    k_scatter<<<GB_E, TB>>>();
    k_node<<<(N_NODES + 31) / 32, 256, NODE_SMEM_BYTES>>>(node_feats, ntl, W_node, W_upd, W_attn);
    k_edge<<<NTILES, 256, EDGE_SMEM_BYTES>>>(edge_attr, edge_type);
    k_aggr<<<N_NODES, 128>>>(out);
}